// round 3
// baseline (speedup 1.0000x reference)
#include <cuda_runtime.h>
#include <cstdint>

// ---------------------------------------------------------------------------
// BinarizedLinear: out = BN( sign(x) @ sign(W)^T )   (bias cancels under BN)
// compute_103 PTX => no tcgen05. Legacy IMMA pipe measured ~264 MACs/cyc/SM
// (93.8% busy) while fma/IMAD pipe (DP4A, ~256 MACs/cyc/SM) sat idle.
// => Hybrid: warps 0-3 mma.sync s8 (cols 0..79), warps 4-7 dp4a (cols 80..127),
// both pipes run concurrently on shared SMEM tiles. Exact integer math.
// ---------------------------------------------------------------------------

#define B_DIM   8192
#define K_DIM   4096
#define O_DIM   4096

__device__ __align__(16) int8_t g_bx8[(size_t)B_DIM * K_DIM];
__device__ __align__(16) int8_t g_bw8[(size_t)O_DIM * K_DIM];
__device__ __align__(16) float g_sum[O_DIM];
__device__ __align__(16) float g_ss[O_DIM];
__device__ __align__(16) float g_scale[O_DIM];
__device__ __align__(16) float g_shift[O_DIM];

// ------------------------------- helpers ------------------------------------
__device__ __forceinline__ uint32_t smem_u32(const void* p) {
    uint32_t a;
    asm("{ .reg .u64 t; cvta.to.shared.u64 t, %1; cvt.u32.u64 %0, t; }" : "=r"(a) : "l"(p));
    return a;
}
__device__ __forceinline__ void cp_async16(uint32_t s, const void* g) {
    asm volatile("cp.async.cg.shared.global [%0], [%1], 16;" :: "r"(s), "l"(g));
}
#define CP_COMMIT() asm volatile("cp.async.commit_group;")

__device__ __forceinline__ void ldsm_x4(uint32_t& r0, uint32_t& r1, uint32_t& r2, uint32_t& r3,
                                        uint32_t addr) {
    asm volatile("ldmatrix.sync.aligned.m8n8.x4.shared.b16 {%0,%1,%2,%3}, [%4];"
                 : "=r"(r0), "=r"(r1), "=r"(r2), "=r"(r3) : "r"(addr));
}
__device__ __forceinline__ void mma_s8(int& c0, int& c1, int& c2, int& c3,
                                       uint32_t a0, uint32_t a1, uint32_t a2, uint32_t a3,
                                       uint32_t b0, uint32_t b1) {
    asm volatile("mma.sync.aligned.m16n8k32.row.col.s32.s8.s8.s32 "
                 "{%0,%1,%2,%3}, {%4,%5,%6,%7}, {%8,%9}, {%0,%1,%2,%3};"
                 : "+r"(c0), "+r"(c1), "+r"(c2), "+r"(c3)
                 : "r"(a0), "r"(a1), "r"(a2), "r"(a3), "r"(b0), "r"(b1));
}

// ------------------------------- binarize -----------------------------------
__device__ __forceinline__ uint32_t pack4(float4 v) {
    uint32_t w = 0;
    float f[4] = {v.x, v.y, v.z, v.w};
#pragma unroll
    for (int j = 0; j < 4; j++) {
        int s = (f[j] > 0.0f) ? 1 : ((f[j] < 0.0f) ? -1 : 0);
        w |= (uint32_t)(uint8_t)(int8_t)s << (8 * j);
    }
    return w;
}
__global__ void binarize_kernel(const float* __restrict__ in, int n16, int which) {
    int8_t* dst = which ? g_bw8 : g_bx8;
    int i = blockIdx.x * blockDim.x + threadIdx.x;
    if (i >= n16) return;
    const float4* p = reinterpret_cast<const float4*>(in) + (size_t)i * 4;
    uint4 o;
    o.x = pack4(p[0]); o.y = pack4(p[1]); o.z = pack4(p[2]); o.w = pack4(p[3]);
    reinterpret_cast<uint4*>(dst)[i] = o;
}

// --------------------------------- GEMM -------------------------------------
// CTA 128(M) x 128(N), KC = 64 B. SMEM A/B: 128 rows x 64 B, double buffered.
// Swizzle: 16B-chunk' = chunk ^ ((row>>1)&3)   (row-phase bijective).
static constexpr int KC = 64;
static constexpr int NKC = K_DIM / KC;              // 64
static constexpr int TILE_B = 128 * 64;             // 8 KB
static constexpr int SMEM_BYTES = 4 * TILE_B + 128;

static constexpr int N_TC = 80;                     // tensor cols per CTA tile
// dp4a handles cols 80..127 (48 cols)

__device__ __forceinline__ uint32_t swz(int row, int cb) {  // cb: 16B chunk 0..3
    return (uint32_t)(row * 64 + ((cb ^ ((row >> 1) & 3)) << 4));
}

__device__ __forceinline__ void load_buf(uint32_t sbase, int m0, int n0, int kc, int tid) {
    const int8_t* ga = g_bx8 + (size_t)m0 * K_DIM + kc * KC;
    const int8_t* gb = g_bw8 + (size_t)n0 * K_DIM + kc * KC;
#pragma unroll
    for (int i = 0; i < 2; i++) {                    // 512 chunks / 256 threads
        int c = tid + i * 256;
        int row = c >> 2, cb = c & 3;
        cp_async16(sbase + swz(row, cb), ga + (size_t)row * K_DIM + cb * 16);
        cp_async16(sbase + TILE_B + swz(row, cb), gb + (size_t)row * K_DIM + cb * 16);
    }
}

__global__ void __launch_bounds__(256) gemm_kernel(float* __restrict__ out) {
    extern __shared__ char smem[];
    uint32_t sb = smem_u32(smem);

    const int tid = threadIdx.x, lane = tid & 31, wid = tid >> 5;
    const int m0 = blockIdx.y * 128, n0 = blockIdx.x * 128;

    // role split
    const bool is_tc = (wid < 4);
    // tensor: warp wid covers rows m0+wid*32 .. +31, cols n0 .. n0+79
    const int lrow = lane & 15;
    const int lk16 = (lane >> 4) & 1;
    // dp4a: warp wd covers rows m0+wd*32 .. +31, cols n0+80 .. n0+127
    const int wd = wid - 4;
    const int gm = lane >> 3;            // 0..3
    const int gn = lane & 7;             // 0..7
    // dp4a lane rows: rowoff(r) = gm*2 + (r&1) + (r>>1)*8   (conflict-free)
    // dp4a lane cols: 80 + c*8 + gn, c = 0..5

    int acc[80];
#pragma unroll
    for (int i = 0; i < 80; i++) acc[i] = 0;

    load_buf(sb, m0, n0, 0, tid);
    CP_COMMIT();

    for (int kc = 0; kc < NKC; kc++) {
        const uint32_t cur = (uint32_t)(kc & 1) * (2 * TILE_B);
        if (kc + 1 < NKC) {
            const uint32_t nxt = (uint32_t)((kc + 1) & 1) * (2 * TILE_B);
            load_buf(sb + nxt, m0, n0, kc + 1, tid);
            CP_COMMIT();
            asm volatile("cp.async.wait_group 1;");
        } else {
            asm volatile("cp.async.wait_group 0;");
        }
        __syncthreads();

        if (is_tc) {
            const uint32_t Ab = sb + cur, Bb = sb + cur + TILE_B;
#pragma unroll
            for (int ks = 0; ks < 2; ks++) {
                const int cb = ks * 2 + lk16;
                uint32_t a[2][4], b[5][4];
#pragma unroll
                for (int mt = 0; mt < 2; mt++)
                    ldsm_x4(a[mt][0], a[mt][1], a[mt][2], a[mt][3],
                            Ab + swz(wid * 32 + mt * 16 + lrow, cb));
#pragma unroll
                for (int bt = 0; bt < 5; bt++)
                    ldsm_x4(b[bt][0], b[bt][1], b[bt][2], b[bt][3],
                            Bb + swz(bt * 16 + lrow, cb));
#pragma unroll
                for (int mt = 0; mt < 2; mt++)
#pragma unroll
                    for (int nt = 0; nt < 10; nt++) {
                        const int ix = (mt * 10 + nt) * 4;
                        uint32_t blo = b[nt >> 1][nt & 1];
                        uint32_t bhi = b[nt >> 1][(nt & 1) + 2];
                        mma_s8(acc[ix], acc[ix + 1], acc[ix + 2], acc[ix + 3],
                               a[mt][0], a[mt][1], a[mt][2], a[mt][3], blo, bhi);
                    }
            }
        } else {
            const char* Abp = smem + cur;
            const char* Bbp = smem + cur + TILE_B;
#pragma unroll
            for (int kw = 0; kw < 4; kw++) {
                uint4 Bv[6];
#pragma unroll
                for (int c = 0; c < 6; c++)
                    Bv[c] = *reinterpret_cast<const uint4*>(Bbp + swz(80 + c * 8 + gn, kw));
#pragma unroll
                for (int r = 0; r < 8; r++) {
                    const int row = wd * 32 + gm * 2 + (r & 1) + (r >> 1) * 8;
                    uint4 Av = *reinterpret_cast<const uint4*>(Abp + swz(row, kw));
#pragma unroll
                    for (int c = 0; c < 6; c++) {
                        int& a0 = acc[r * 6 + c];
                        a0 = __dp4a((int)Av.x, (int)Bv[c].x, a0);
                        a0 = __dp4a((int)Av.y, (int)Bv[c].y, a0);
                        a0 = __dp4a((int)Av.z, (int)Bv[c].z, a0);
                        a0 = __dp4a((int)Av.w, (int)Bv[c].w, a0);
                    }
                }
            }
        }
        __syncthreads();
    }

    // ----------------------------- epilogue ---------------------------------
    if (is_tc) {
        const int gq = lane >> 2, tg = lane & 3;
#pragma unroll
        for (int mt = 0; mt < 2; mt++) {
#pragma unroll
            for (int nt = 0; nt < 10; nt++) {
                const int ix = (mt * 10 + nt) * 4;
                int col = n0 + nt * 8 + 2 * tg;
                int row0 = m0 + wid * 32 + mt * 16 + gq;
                float2 v0 = make_float2((float)acc[ix], (float)acc[ix + 1]);
                float2 v1 = make_float2((float)acc[ix + 2], (float)acc[ix + 3]);
                *reinterpret_cast<float2*>(out + (size_t)row0 * O_DIM + col) = v0;
                *reinterpret_cast<float2*>(out + (size_t)(row0 + 8) * O_DIM + col) = v1;
            }
        }
    } else {
#pragma unroll
        for (int r = 0; r < 8; r++) {
            const int row = m0 + wd * 32 + gm * 2 + (r & 1) + (r >> 1) * 8;
#pragma unroll
            for (int c = 0; c < 6; c++) {
                out[(size_t)row * O_DIM + n0 + 80 + c * 8 + gn] = (float)acc[r * 6 + c];
            }
        }
    }
}

// ------------------------------ BatchNorm -----------------------------------
__global__ void bn_zero() {
    int i = blockIdx.x * blockDim.x + threadIdx.x;
    if (i < O_DIM) { g_sum[i] = 0.f; g_ss[i] = 0.f; }
}
__global__ void bn_reduce(const float* __restrict__ d) {
    int col = blockIdx.x * 256 + threadIdx.x;
    const float* p = d + (size_t)blockIdx.y * 256 * O_DIM + col;
    float s = 0.f, ss = 0.f;
#pragma unroll 8
    for (int r = 0; r < 256; r++) {
        float v = p[(size_t)r * O_DIM];
        s += v;
        ss = fmaf(v, v, ss);
    }
    atomicAdd(&g_sum[col], s);
    atomicAdd(&g_ss[col], ss);
}
__global__ void bn_params() {
    int c = blockIdx.x * blockDim.x + threadIdx.x;
    if (c < O_DIM) {
        float mean = g_sum[c] * (1.0f / B_DIM);
        float var = g_ss[c] * (1.0f / B_DIM) - mean * mean;
        float sc = rsqrtf(var + 1e-5f);
        g_scale[c] = sc;
        g_shift[c] = -mean * sc;
    }
}
__global__ void bn_apply(float* __restrict__ d) {
    int i = blockIdx.x * blockDim.x + threadIdx.x;
    float4 v = reinterpret_cast<float4*>(d)[i];
    int c = (i & (O_DIM / 4 - 1)) << 2;
    float4 sc = *reinterpret_cast<const float4*>(g_scale + c);
    float4 sh = *reinterpret_cast<const float4*>(g_shift + c);
    v.x = fmaf(v.x, sc.x, sh.x);
    v.y = fmaf(v.y, sc.y, sh.y);
    v.z = fmaf(v.z, sc.z, sh.z);
    v.w = fmaf(v.w, sc.w, sh.w);
    reinterpret_cast<float4*>(d)[i] = v;
}

// -------------------------------- launch -------------------------------------
extern "C" void kernel_launch(void* const* d_in, const int* in_sizes, int n_in,
                              void* d_out, int out_size) {
    const float* x = (const float*)d_in[0];
    const float* w = (const float*)d_in[1];
    float* out = (float*)d_out;

    binarize_kernel<<<(B_DIM * K_DIM / 16) / 256, 256>>>(x, B_DIM * K_DIM / 16, 0);
    binarize_kernel<<<(O_DIM * K_DIM / 16) / 256, 256>>>(w, O_DIM * K_DIM / 16, 1);
    bn_zero<<<16, 256>>>();

    gemm_kernel<<<dim3(O_DIM / 128, B_DIM / 128), 256, SMEM_BYTES>>>(out);

    bn_reduce<<<dim3(O_DIM / 256, B_DIM / 256), 256>>>(out);
    bn_params<<<16, 256>>>();
    bn_apply<<<(B_DIM * O_DIM / 4) / 256, 256>>>(out);
}

// round 4
// speedup vs baseline: 1.1256x; 1.1256x over previous
#include <cuda_runtime.h>
#include <cstdint>

// ---------------------------------------------------------------------------
// BinarizedLinear: out = BN( sign(x) @ sign(W)^T )   (bias cancels under BN)
// compute_103 PTX => no tcgen05. Dual-pipe GEMM:
//   8 tensor warps: mma.sync m16n8k32 s8 on cols 0..95   (legacy pipe ~297 MAC/cyc/SM)
//   4 dp4a warps:   __dp4a on cols 96..127               (fma pipe, rt~5/SMSP)
// Balanced so tensor (2650 cyc/kc) >= dp4a (2560 cyc/kc). Exact integer math.
// ---------------------------------------------------------------------------

#define B_DIM   8192
#define K_DIM   4096
#define O_DIM   4096

__device__ __align__(16) int8_t g_bx8[(size_t)B_DIM * K_DIM];
__device__ __align__(16) int8_t g_bw8[(size_t)O_DIM * K_DIM];
__device__ __align__(16) float g_sum[O_DIM];
__device__ __align__(16) float g_ss[O_DIM];
__device__ __align__(16) float g_scale[O_DIM];
__device__ __align__(16) float g_shift[O_DIM];

// ------------------------------- helpers ------------------------------------
__device__ __forceinline__ uint32_t smem_u32(const void* p) {
    uint32_t a;
    asm("{ .reg .u64 t; cvta.to.shared.u64 t, %1; cvt.u32.u64 %0, t; }" : "=r"(a) : "l"(p));
    return a;
}
__device__ __forceinline__ void cp_async16(uint32_t s, const void* g) {
    asm volatile("cp.async.cg.shared.global [%0], [%1], 16;" :: "r"(s), "l"(g));
}
#define CP_COMMIT() asm volatile("cp.async.commit_group;")

__device__ __forceinline__ void ldsm_x4(uint32_t& r0, uint32_t& r1, uint32_t& r2, uint32_t& r3,
                                        uint32_t addr) {
    asm volatile("ldmatrix.sync.aligned.m8n8.x4.shared.b16 {%0,%1,%2,%3}, [%4];"
                 : "=r"(r0), "=r"(r1), "=r"(r2), "=r"(r3) : "r"(addr));
}
__device__ __forceinline__ void mma_s8(int& c0, int& c1, int& c2, int& c3,
                                       uint32_t a0, uint32_t a1, uint32_t a2, uint32_t a3,
                                       uint32_t b0, uint32_t b1) {
    asm volatile("mma.sync.aligned.m16n8k32.row.col.s32.s8.s8.s32 "
                 "{%0,%1,%2,%3}, {%4,%5,%6,%7}, {%8,%9}, {%0,%1,%2,%3};"
                 : "+r"(c0), "+r"(c1), "+r"(c2), "+r"(c3)
                 : "r"(a0), "r"(a1), "r"(a2), "r"(a3), "r"(b0), "r"(b1));
}

// ------------------------------- binarize -----------------------------------
__device__ __forceinline__ uint32_t pack4(float4 v) {
    uint32_t w = 0;
    float f[4] = {v.x, v.y, v.z, v.w};
#pragma unroll
    for (int j = 0; j < 4; j++) {
        int s = (f[j] > 0.0f) ? 1 : ((f[j] < 0.0f) ? -1 : 0);
        w |= (uint32_t)(uint8_t)(int8_t)s << (8 * j);
    }
    return w;
}
// One kernel for both tensors: first nx16 chunks -> g_bx8, rest -> g_bw8.
__global__ void binarize_all(const float* __restrict__ x, const float* __restrict__ w,
                             int nx16, int ntot16) {
    int i = blockIdx.x * blockDim.x + threadIdx.x;
    if (i >= ntot16) return;
    const float* src;
    int8_t* dst;
    int j;
    if (i < nx16) { src = x; dst = g_bx8; j = i; }
    else          { src = w; dst = g_bw8; j = i - nx16; }
    const float4* p = reinterpret_cast<const float4*>(src) + (size_t)j * 4;
    uint4 o;
    o.x = pack4(p[0]); o.y = pack4(p[1]); o.z = pack4(p[2]); o.w = pack4(p[3]);
    reinterpret_cast<uint4*>(dst)[j] = o;
}

// --------------------------------- GEMM -------------------------------------
static constexpr int KC = 64;
static constexpr int NKC = K_DIM / KC;              // 64
static constexpr int TILE_B = 128 * 64;             // 8 KB
static constexpr int SMEM_BYTES = 4 * TILE_B + 128;
static constexpr int NTHREADS = 384;

__device__ __forceinline__ uint32_t swz(int row, int cb) {  // cb: 16B chunk 0..3
    return (uint32_t)(row * 64 + ((cb ^ ((row >> 1) & 3)) << 4));
}

__device__ __forceinline__ void load_buf(uint32_t sbase, int m0, int n0, int kc, int tid) {
    const int8_t* ga = g_bx8 + (size_t)m0 * K_DIM + kc * KC;
    const int8_t* gb = g_bw8 + (size_t)n0 * K_DIM + kc * KC;
#pragma unroll
    for (int i = 0; i < 3; i++) {                    // 1024 chunks / 384 threads
        int c = tid + i * NTHREADS;
        if (c < 512) {
            int row = c >> 2, cb = c & 3;
            cp_async16(sbase + swz(row, cb), ga + (size_t)row * K_DIM + cb * 16);
        } else if (c < 1024) {
            int c2 = c - 512;
            int row = c2 >> 2, cb = c2 & 3;
            cp_async16(sbase + TILE_B + swz(row, cb), gb + (size_t)row * K_DIM + cb * 16);
        }
    }
}

__global__ void __launch_bounds__(NTHREADS) gemm_kernel(float* __restrict__ out) {
    extern __shared__ char smem[];
    uint32_t sb = smem_u32(smem);

    const int tid = threadIdx.x, lane = tid & 31, wid = tid >> 5;
    const int m0 = blockIdx.y * 128, n0 = blockIdx.x * 128;

    const bool is_tc = (wid < 8);
    // tensor: warp grid 4(M) x 2(N); warp tile 32M x 48N over cols 0..95
    const int wm = (wid & 3) * 32, wn = (wid >> 2) * 48;
    const int lrow = lane & 15;
    const int lk16 = (lane >> 4) & 1;
    // dp4a: warps 8..11 (one per SMSP); cols 96..127, rows wd*32..+31
    const int wd = wid - 8;
    const int gm = lane >> 3;            // 0..3
    const int gn = lane & 7;             // 0..7

    int acc[48];
#pragma unroll
    for (int i = 0; i < 48; i++) acc[i] = 0;

    load_buf(sb, m0, n0, 0, tid);
    CP_COMMIT();

    for (int kc = 0; kc < NKC; kc++) {
        const uint32_t cur = (uint32_t)(kc & 1) * (2 * TILE_B);
        if (kc + 1 < NKC) {
            const uint32_t nxt = (uint32_t)((kc + 1) & 1) * (2 * TILE_B);
            load_buf(sb + nxt, m0, n0, kc + 1, tid);
            CP_COMMIT();
            asm volatile("cp.async.wait_group 1;");
        } else {
            asm volatile("cp.async.wait_group 0;");
        }
        __syncthreads();

        if (is_tc) {
            const uint32_t Ab = sb + cur, Bb = sb + cur + TILE_B;
#pragma unroll
            for (int ks = 0; ks < 2; ks++) {
                const int cb = ks * 2 + lk16;
                uint32_t a[2][4], b[3][4];
#pragma unroll
                for (int mt = 0; mt < 2; mt++)
                    ldsm_x4(a[mt][0], a[mt][1], a[mt][2], a[mt][3],
                            Ab + swz(wm + mt * 16 + lrow, cb));
#pragma unroll
                for (int bt = 0; bt < 3; bt++)
                    ldsm_x4(b[bt][0], b[bt][1], b[bt][2], b[bt][3],
                            Bb + swz(wn + bt * 16 + lrow, cb));
#pragma unroll
                for (int mt = 0; mt < 2; mt++)
#pragma unroll
                    for (int nt = 0; nt < 6; nt++) {
                        const int ix = (mt * 6 + nt) * 4;
                        uint32_t blo = b[nt >> 1][nt & 1];
                        uint32_t bhi = b[nt >> 1][(nt & 1) + 2];
                        mma_s8(acc[ix], acc[ix + 1], acc[ix + 2], acc[ix + 3],
                               a[mt][0], a[mt][1], a[mt][2], a[mt][3], blo, bhi);
                    }
            }
        } else {
            const char* Abp = smem + cur;
            const char* Bbp = smem + cur + TILE_B;
#pragma unroll
            for (int kw = 0; kw < 4; kw++) {
                uint4 Bv[4];
#pragma unroll
                for (int c = 0; c < 4; c++)
                    Bv[c] = *reinterpret_cast<const uint4*>(Bbp + swz(96 + c * 8 + gn, kw));
#pragma unroll
                for (int r = 0; r < 8; r++) {
                    const int row = wd * 32 + gm * 2 + (r & 1) + (r >> 1) * 8;
                    uint4 Av = *reinterpret_cast<const uint4*>(Abp + swz(row, kw));
#pragma unroll
                    for (int c = 0; c < 4; c++) {
                        int& a0 = acc[r * 4 + c];
                        a0 = __dp4a((int)Av.x, (int)Bv[c].x, a0);
                        a0 = __dp4a((int)Av.y, (int)Bv[c].y, a0);
                        a0 = __dp4a((int)Av.z, (int)Bv[c].z, a0);
                        a0 = __dp4a((int)Av.w, (int)Bv[c].w, a0);
                    }
                }
            }
        }
        __syncthreads();
    }

    // ----------------------------- epilogue ---------------------------------
    if (is_tc) {
        const int gq = lane >> 2, tg = lane & 3;
#pragma unroll
        for (int mt = 0; mt < 2; mt++) {
#pragma unroll
            for (int nt = 0; nt < 6; nt++) {
                const int ix = (mt * 6 + nt) * 4;
                int col = n0 + wn + nt * 8 + 2 * tg;
                int row0 = m0 + wm + mt * 16 + gq;
                float2 v0 = make_float2((float)acc[ix], (float)acc[ix + 1]);
                float2 v1 = make_float2((float)acc[ix + 2], (float)acc[ix + 3]);
                *reinterpret_cast<float2*>(out + (size_t)row0 * O_DIM + col) = v0;
                *reinterpret_cast<float2*>(out + (size_t)(row0 + 8) * O_DIM + col) = v1;
            }
        }
    } else {
#pragma unroll
        for (int r = 0; r < 8; r++) {
            const int row = m0 + wd * 32 + gm * 2 + (r & 1) + (r >> 1) * 8;
#pragma unroll
            for (int c = 0; c < 4; c++) {
                out[(size_t)row * O_DIM + n0 + 96 + c * 8 + gn] = (float)acc[r * 4 + c];
            }
        }
    }
}

// ------------------------------ BatchNorm -----------------------------------
__global__ void bn_zero() {
    int i = blockIdx.x * blockDim.x + threadIdx.x;
    if (i < O_DIM) { g_sum[i] = 0.f; g_ss[i] = 0.f; }
}
__global__ void bn_reduce(const float* __restrict__ d) {
    int col = blockIdx.x * 256 + threadIdx.x;
    const float* p = d + (size_t)blockIdx.y * 256 * O_DIM + col;
    float s = 0.f, ss = 0.f;
#pragma unroll 8
    for (int r = 0; r < 256; r++) {
        float v = p[(size_t)r * O_DIM];
        s += v;
        ss = fmaf(v, v, ss);
    }
    atomicAdd(&g_sum[col], s);
    atomicAdd(&g_ss[col], ss);
}
__global__ void bn_params() {
    int c = blockIdx.x * blockDim.x + threadIdx.x;
    if (c < O_DIM) {
        float mean = g_sum[c] * (1.0f / B_DIM);
        float var = g_ss[c] * (1.0f / B_DIM) - mean * mean;
        float sc = rsqrtf(var + 1e-5f);
        g_scale[c] = sc;
        g_shift[c] = -mean * sc;
    }
}
__global__ void bn_apply(float* __restrict__ d) {
    int i = blockIdx.x * blockDim.x + threadIdx.x;
    float4 v = reinterpret_cast<float4*>(d)[i];
    int c = (i & (O_DIM / 4 - 1)) << 2;
    float4 sc = *reinterpret_cast<const float4*>(g_scale + c);
    float4 sh = *reinterpret_cast<const float4*>(g_shift + c);
    v.x = fmaf(v.x, sc.x, sh.x);
    v.y = fmaf(v.y, sc.y, sh.y);
    v.z = fmaf(v.z, sc.z, sh.z);
    v.w = fmaf(v.w, sc.w, sh.w);
    reinterpret_cast<float4*>(d)[i] = v;
}

// -------------------------------- launch -------------------------------------
extern "C" void kernel_launch(void* const* d_in, const int* in_sizes, int n_in,
                              void* d_out, int out_size) {
    const float* x = (const float*)d_in[0];
    const float* w = (const float*)d_in[1];
    float* out = (float*)d_out;

    const int nx16 = B_DIM * K_DIM / 16;
    const int nt16 = nx16 + O_DIM * K_DIM / 16;
    binarize_all<<<(nt16 + 255) / 256, 256>>>(x, w, nx16, nt16);
    bn_zero<<<16, 256>>>();

    gemm_kernel<<<dim3(O_DIM / 128, B_DIM / 128), NTHREADS, SMEM_BYTES>>>(out);

    bn_reduce<<<dim3(O_DIM / 256, B_DIM / 256), 256>>>(out);
    bn_params<<<16, 256>>>();
    bn_apply<<<(B_DIM * O_DIM / 4) / 256, 256>>>(out);
}

// round 5
// speedup vs baseline: 1.2525x; 1.1128x over previous
#include <cuda_runtime.h>
#include <cstdint>

// ---------------------------------------------------------------------------
// BinarizedLinear: out = BN( sign(x) @ sign(W)^T )   (bias cancels under BN)
// compute_103 PTX => no tcgen05. Dual-pipe GEMM:
//   8 tensor warps: mma.sync m16n8k32 s8 on cols 0..95
//   4 dp4a warps:   __dp4a on cols 96..127 (fma pipe)
// R5: KC=128 (half the barriers), 2 CTAs/SM (hide barrier/load stalls).
// ---------------------------------------------------------------------------

#define B_DIM   8192
#define K_DIM   4096
#define O_DIM   4096

__device__ __align__(16) int8_t g_bx8[(size_t)B_DIM * K_DIM];
__device__ __align__(16) int8_t g_bw8[(size_t)O_DIM * K_DIM];
__device__ __align__(16) float g_sum[O_DIM];
__device__ __align__(16) float g_ss[O_DIM];
__device__ __align__(16) float g_scale[O_DIM];
__device__ __align__(16) float g_shift[O_DIM];

// ------------------------------- helpers ------------------------------------
__device__ __forceinline__ uint32_t smem_u32(const void* p) {
    uint32_t a;
    asm("{ .reg .u64 t; cvta.to.shared.u64 t, %1; cvt.u32.u64 %0, t; }" : "=r"(a) : "l"(p));
    return a;
}
__device__ __forceinline__ void cp_async16(uint32_t s, const void* g) {
    asm volatile("cp.async.cg.shared.global [%0], [%1], 16;" :: "r"(s), "l"(g));
}
#define CP_COMMIT() asm volatile("cp.async.commit_group;")

__device__ __forceinline__ void ldsm_x4(uint32_t& r0, uint32_t& r1, uint32_t& r2, uint32_t& r3,
                                        uint32_t addr) {
    asm volatile("ldmatrix.sync.aligned.m8n8.x4.shared.b16 {%0,%1,%2,%3}, [%4];"
                 : "=r"(r0), "=r"(r1), "=r"(r2), "=r"(r3) : "r"(addr));
}
__device__ __forceinline__ void mma_s8(int& c0, int& c1, int& c2, int& c3,
                                       uint32_t a0, uint32_t a1, uint32_t a2, uint32_t a3,
                                       uint32_t b0, uint32_t b1) {
    asm volatile("mma.sync.aligned.m16n8k32.row.col.s32.s8.s8.s32 "
                 "{%0,%1,%2,%3}, {%4,%5,%6,%7}, {%8,%9}, {%0,%1,%2,%3};"
                 : "+r"(c0), "+r"(c1), "+r"(c2), "+r"(c3)
                 : "r"(a0), "r"(a1), "r"(a2), "r"(a3), "r"(b0), "r"(b1));
}

// ------------------------------- binarize -----------------------------------
__device__ __forceinline__ uint32_t pack4(float4 v) {
    uint32_t w = 0;
    float f[4] = {v.x, v.y, v.z, v.w};
#pragma unroll
    for (int j = 0; j < 4; j++) {
        int s = (f[j] > 0.0f) ? 1 : ((f[j] < 0.0f) ? -1 : 0);
        w |= (uint32_t)(uint8_t)(int8_t)s << (8 * j);
    }
    return w;
}
__global__ void binarize_all(const float* __restrict__ x, const float* __restrict__ w,
                             int nx16, int ntot16) {
    int i = blockIdx.x * blockDim.x + threadIdx.x;
    if (i >= ntot16) return;
    const float* src;
    int8_t* dst;
    int j;
    if (i < nx16) { src = x; dst = g_bx8; j = i; }
    else          { src = w; dst = g_bw8; j = i - nx16; }
    const float4* p = reinterpret_cast<const float4*>(src) + (size_t)j * 4;
    uint4 o;
    o.x = pack4(p[0]); o.y = pack4(p[1]); o.z = pack4(p[2]); o.w = pack4(p[3]);
    reinterpret_cast<uint4*>(dst)[j] = o;
}

// --------------------------------- GEMM -------------------------------------
// CTA 128(M) x 128(N). KC = 128 B (full SW128 swizzle row). Double buffered.
static constexpr int KC = 128;
static constexpr int NKC = K_DIM / KC;              // 32
static constexpr int TILE_B = 128 * 128;            // 16 KB per operand
static constexpr int SMEM_BYTES = 4 * TILE_B;       // 64 KB (2 bufs x A,B)
static constexpr int NTHREADS = 384;

__device__ __forceinline__ uint32_t swz(int row, int cb) {  // cb: 16B chunk 0..7
    return (uint32_t)(row * 128 + ((cb ^ (row & 7)) << 4));
}

__device__ __forceinline__ void load_buf(uint32_t sbase, int m0, int n0, int kc, int tid) {
    const int8_t* ga = g_bx8 + (size_t)m0 * K_DIM + kc * KC;
    const int8_t* gb = g_bw8 + (size_t)n0 * K_DIM + kc * KC;
#pragma unroll
    for (int i = 0; i < 6; i++) {                    // 2048 chunks / 384 threads
        int c = tid + i * NTHREADS;
        if (c < 1024) {
            int row = c >> 3, cb = c & 7;
            cp_async16(sbase + swz(row, cb), ga + (size_t)row * K_DIM + cb * 16);
        } else if (c < 2048) {
            int c2 = c - 1024;
            int row = c2 >> 3, cb = c2 & 7;
            cp_async16(sbase + TILE_B + swz(row, cb), gb + (size_t)row * K_DIM + cb * 16);
        }
    }
}

__global__ void __launch_bounds__(NTHREADS, 2) gemm_kernel(float* __restrict__ out) {
    extern __shared__ char smem[];
    uint32_t sb = smem_u32(smem);

    const int tid = threadIdx.x, lane = tid & 31, wid = tid >> 5;
    const int m0 = blockIdx.y * 128, n0 = blockIdx.x * 128;

    const bool is_tc = (wid < 8);
    // tensor: warp grid 4(M) x 2(N); warp tile 32M x 48N over cols 0..95
    const int wm = (wid & 3) * 32, wn = (wid >> 2) * 48;
    const int lrow = lane & 15;
    const int lk16 = (lane >> 4) & 1;
    // dp4a: warps 8..11; cols 96..127, rows wd*32..+31
    const int wd = wid - 8;
    const int gm = lane >> 3;            // 0..3
    const int gn = lane & 7;             // 0..7

    int acc[48];
#pragma unroll
    for (int i = 0; i < 48; i++) acc[i] = 0;

    load_buf(sb, m0, n0, 0, tid);
    CP_COMMIT();

    for (int kc = 0; kc < NKC; kc++) {
        const uint32_t cur = (uint32_t)(kc & 1) * (2 * TILE_B);
        if (kc + 1 < NKC) {
            const uint32_t nxt = (uint32_t)((kc + 1) & 1) * (2 * TILE_B);
            load_buf(sb + nxt, m0, n0, kc + 1, tid);
            CP_COMMIT();
            asm volatile("cp.async.wait_group 1;");
        } else {
            asm volatile("cp.async.wait_group 0;");
        }
        __syncthreads();

        if (is_tc) {
            const uint32_t Ab = sb + cur, Bb = sb + cur + TILE_B;
#pragma unroll
            for (int ks = 0; ks < 4; ks++) {
                const int cb = ks * 2 + lk16;        // 16B chunk 0..7
                uint32_t a[2][4], b[3][4];
#pragma unroll
                for (int mt = 0; mt < 2; mt++)
                    ldsm_x4(a[mt][0], a[mt][1], a[mt][2], a[mt][3],
                            Ab + swz(wm + mt * 16 + lrow, cb));
#pragma unroll
                for (int bt = 0; bt < 3; bt++)
                    ldsm_x4(b[bt][0], b[bt][1], b[bt][2], b[bt][3],
                            Bb + swz(wn + bt * 16 + lrow, cb));
#pragma unroll
                for (int mt = 0; mt < 2; mt++)
#pragma unroll
                    for (int nt = 0; nt < 6; nt++) {
                        const int ix = (mt * 6 + nt) * 4;
                        uint32_t blo = b[nt >> 1][nt & 1];
                        uint32_t bhi = b[nt >> 1][(nt & 1) + 2];
                        mma_s8(acc[ix], acc[ix + 1], acc[ix + 2], acc[ix + 3],
                               a[mt][0], a[mt][1], a[mt][2], a[mt][3], blo, bhi);
                    }
            }
        } else {
            const char* Abp = smem + cur;
            const char* Bbp = smem + cur + TILE_B;
#pragma unroll
            for (int kw = 0; kw < 8; kw++) {
                uint4 Bv[4];
#pragma unroll
                for (int c = 0; c < 4; c++)
                    Bv[c] = *reinterpret_cast<const uint4*>(Bbp + swz(96 + c * 8 + gn, kw));
#pragma unroll
                for (int r = 0; r < 8; r++) {
                    const int row = wd * 32 + gm * 2 + (r & 1) + (r >> 1) * 8;
                    uint4 Av = *reinterpret_cast<const uint4*>(Abp + swz(row, kw));
#pragma unroll
                    for (int c = 0; c < 4; c++) {
                        int& a0 = acc[r * 4 + c];
                        a0 = __dp4a((int)Av.x, (int)Bv[c].x, a0);
                        a0 = __dp4a((int)Av.y, (int)Bv[c].y, a0);
                        a0 = __dp4a((int)Av.z, (int)Bv[c].z, a0);
                        a0 = __dp4a((int)Av.w, (int)Bv[c].w, a0);
                    }
                }
            }
        }
        __syncthreads();
    }

    // ----------------------------- epilogue ---------------------------------
    if (is_tc) {
        const int gq = lane >> 2, tg = lane & 3;
#pragma unroll
        for (int mt = 0; mt < 2; mt++) {
#pragma unroll
            for (int nt = 0; nt < 6; nt++) {
                const int ix = (mt * 6 + nt) * 4;
                int col = n0 + wn + nt * 8 + 2 * tg;
                int row0 = m0 + wm + mt * 16 + gq;
                float2 v0 = make_float2((float)acc[ix], (float)acc[ix + 1]);
                float2 v1 = make_float2((float)acc[ix + 2], (float)acc[ix + 3]);
                *reinterpret_cast<float2*>(out + (size_t)row0 * O_DIM + col) = v0;
                *reinterpret_cast<float2*>(out + (size_t)(row0 + 8) * O_DIM + col) = v1;
            }
        }
    } else {
#pragma unroll
        for (int r = 0; r < 8; r++) {
            const int row = m0 + wd * 32 + gm * 2 + (r & 1) + (r >> 1) * 8;
#pragma unroll
            for (int c = 0; c < 4; c++) {
                out[(size_t)row * O_DIM + n0 + 96 + c * 8 + gn] = (float)acc[r * 4 + c];
            }
        }
    }
}

// ------------------------------ BatchNorm -----------------------------------
__global__ void bn_zero() {
    int i = blockIdx.x * blockDim.x + threadIdx.x;
    if (i < O_DIM) { g_sum[i] = 0.f; g_ss[i] = 0.f; }
}
__global__ void bn_reduce(const float* __restrict__ d) {
    int col = blockIdx.x * 256 + threadIdx.x;
    const float* p = d + (size_t)blockIdx.y * 256 * O_DIM + col;
    float s = 0.f, ss = 0.f;
#pragma unroll 8
    for (int r = 0; r < 256; r++) {
        float v = p[(size_t)r * O_DIM];
        s += v;
        ss = fmaf(v, v, ss);
    }
    atomicAdd(&g_sum[col], s);
    atomicAdd(&g_ss[col], ss);
}
__global__ void bn_params() {
    int c = blockIdx.x * blockDim.x + threadIdx.x;
    if (c < O_DIM) {
        float mean = g_sum[c] * (1.0f / B_DIM);
        float var = g_ss[c] * (1.0f / B_DIM) - mean * mean;
        float sc = rsqrtf(var + 1e-5f);
        g_scale[c] = sc;
        g_shift[c] = -mean * sc;
    }
}
__global__ void bn_apply(float* __restrict__ d) {
    int i = blockIdx.x * blockDim.x + threadIdx.x;
    float4 v = reinterpret_cast<float4*>(d)[i];
    int c = (i & (O_DIM / 4 - 1)) << 2;
    float4 sc = *reinterpret_cast<const float4*>(g_scale + c);
    float4 sh = *reinterpret_cast<const float4*>(g_shift + c);
    v.x = fmaf(v.x, sc.x, sh.x);
    v.y = fmaf(v.y, sc.y, sh.y);
    v.z = fmaf(v.z, sc.z, sh.z);
    v.w = fmaf(v.w, sc.w, sh.w);
    reinterpret_cast<float4*>(d)[i] = v;
}

// -------------------------------- launch -------------------------------------
extern "C" void kernel_launch(void* const* d_in, const int* in_sizes, int n_in,
                              void* d_out, int out_size) {
    const float* x = (const float*)d_in[0];
    const float* w = (const float*)d_in[1];
    float* out = (float*)d_out;

    cudaFuncSetAttribute(gemm_kernel, cudaFuncAttributeMaxDynamicSharedMemorySize, SMEM_BYTES);

    const int nx16 = B_DIM * K_DIM / 16;
    const int nt16 = nx16 + O_DIM * K_DIM / 16;
    binarize_all<<<(nt16 + 255) / 256, 256>>>(x, w, nx16, nt16);
    bn_zero<<<16, 256>>>();

    gemm_kernel<<<dim3(O_DIM / 128, B_DIM / 128), NTHREADS, SMEM_BYTES>>>(out);

    bn_reduce<<<dim3(O_DIM / 256, B_DIM / 256), 256>>>(out);
    bn_params<<<16, 256>>>();
    bn_apply<<<(B_DIM * O_DIM / 4) / 256, 256>>>(out);
}

// round 6
// speedup vs baseline: 1.3815x; 1.1030x over previous
#include <cuda_runtime.h>
#include <cstdint>

// ---------------------------------------------------------------------------
// BinarizedLinear: out = BN( sign(x) @ sign(W)^T )   (bias cancels under BN)
// compute_103 PTX => no tcgen05. Dual-pipe GEMM, R6:
//   8 tensor warps: mma.sync m16n8k32 s8, warp tile 16M x 80N (cols 0..79)
//   4 dp4a warps:   __dp4a on cols 80..127 (fma pipe, ~2.25 cyc/instr @2 warps/SMSP)
//   3-stage cp.async pipeline, ONE barrier per k-chunk, 2 CTAs/SM.
// ---------------------------------------------------------------------------

#define B_DIM   8192
#define K_DIM   4096
#define O_DIM   4096

__device__ __align__(16) int8_t g_bx8[(size_t)B_DIM * K_DIM];
__device__ __align__(16) int8_t g_bw8[(size_t)O_DIM * K_DIM];
__device__ __align__(16) float g_sum[O_DIM];
__device__ __align__(16) float g_ss[O_DIM];
__device__ __align__(16) float g_scale[O_DIM];
__device__ __align__(16) float g_shift[O_DIM];

// ------------------------------- helpers ------------------------------------
__device__ __forceinline__ uint32_t smem_u32(const void* p) {
    uint32_t a;
    asm("{ .reg .u64 t; cvta.to.shared.u64 t, %1; cvt.u32.u64 %0, t; }" : "=r"(a) : "l"(p));
    return a;
}
__device__ __forceinline__ void cp_async16(uint32_t s, const void* g) {
    asm volatile("cp.async.cg.shared.global [%0], [%1], 16;" :: "r"(s), "l"(g));
}
#define CP_COMMIT() asm volatile("cp.async.commit_group;")

__device__ __forceinline__ void ldsm_x4(uint32_t& r0, uint32_t& r1, uint32_t& r2, uint32_t& r3,
                                        uint32_t addr) {
    asm volatile("ldmatrix.sync.aligned.m8n8.x4.shared.b16 {%0,%1,%2,%3}, [%4];"
                 : "=r"(r0), "=r"(r1), "=r"(r2), "=r"(r3) : "r"(addr));
}
__device__ __forceinline__ void mma_s8(int& c0, int& c1, int& c2, int& c3,
                                       uint32_t a0, uint32_t a1, uint32_t a2, uint32_t a3,
                                       uint32_t b0, uint32_t b1) {
    asm volatile("mma.sync.aligned.m16n8k32.row.col.s32.s8.s8.s32 "
                 "{%0,%1,%2,%3}, {%4,%5,%6,%7}, {%8,%9}, {%0,%1,%2,%3};"
                 : "+r"(c0), "+r"(c1), "+r"(c2), "+r"(c3)
                 : "r"(a0), "r"(a1), "r"(a2), "r"(a3), "r"(b0), "r"(b1));
}

// ------------------------------- binarize -----------------------------------
__device__ __forceinline__ uint32_t pack4(float4 v) {
    uint32_t w = 0;
    float f[4] = {v.x, v.y, v.z, v.w};
#pragma unroll
    for (int j = 0; j < 4; j++) {
        int s = (f[j] > 0.0f) ? 1 : ((f[j] < 0.0f) ? -1 : 0);
        w |= (uint32_t)(uint8_t)(int8_t)s << (8 * j);
    }
    return w;
}
__global__ void binarize_all(const float* __restrict__ x, const float* __restrict__ w,
                             int nx16, int ntot16) {
    int i = blockIdx.x * blockDim.x + threadIdx.x;
    if (i >= ntot16) return;
    const float* src;
    int8_t* dst;
    int j;
    if (i < nx16) { src = x; dst = g_bx8; j = i; }
    else          { src = w; dst = g_bw8; j = i - nx16; }
    const float4* p = reinterpret_cast<const float4*>(src) + (size_t)j * 4;
    uint4 o;
    o.x = pack4(p[0]); o.y = pack4(p[1]); o.z = pack4(p[2]); o.w = pack4(p[3]);
    reinterpret_cast<uint4*>(dst)[j] = o;
}

// --------------------------------- GEMM -------------------------------------
// CTA 128(M) x 128(N). KC = 128 B. 3 SMEM stages, one barrier per kc.
static constexpr int KC = 128;
static constexpr int NKC = K_DIM / KC;              // 32
static constexpr int TILE_B = 128 * 128;            // 16 KB per operand
static constexpr int STAGE_B = 2 * TILE_B;          // 32 KB (A+B)
static constexpr int SMEM_BYTES = 3 * STAGE_B;      // 96 KB
static constexpr int NTHREADS = 384;

__device__ __forceinline__ uint32_t swz(int row, int cb) {  // cb: 16B chunk 0..7
    return (uint32_t)(row * 128 + ((cb ^ (row & 7)) << 4));
}

__device__ __forceinline__ void load_buf(uint32_t sbase, int m0, int n0, int kc, int tid) {
    const int8_t* ga = g_bx8 + (size_t)m0 * K_DIM + kc * KC;
    const int8_t* gb = g_bw8 + (size_t)n0 * K_DIM + kc * KC;
#pragma unroll
    for (int i = 0; i < 6; i++) {                    // 2048 chunks / 384 threads
        int c = tid + i * NTHREADS;
        if (c < 1024) {
            int row = c >> 3, cb = c & 7;
            cp_async16(sbase + swz(row, cb), ga + (size_t)row * K_DIM + cb * 16);
        } else if (c < 2048) {
            int c2 = c - 1024;
            int row = c2 >> 3, cb = c2 & 7;
            cp_async16(sbase + TILE_B + swz(row, cb), gb + (size_t)row * K_DIM + cb * 16);
        }
    }
}

__global__ void __launch_bounds__(NTHREADS, 2) gemm_kernel(float* __restrict__ out) {
    extern __shared__ char smem[];
    uint32_t sb = smem_u32(smem);

    const int tid = threadIdx.x, lane = tid & 31, wid = tid >> 5;
    const int m0 = blockIdx.y * 128, n0 = blockIdx.x * 128;

    const bool is_tc = (wid < 8);
    // tensor: warp tile 16M x 80N; rows wid*16..+15, cols 0..79
    const int wm = wid * 16;
    const int lrow = lane & 15;
    const int lk16 = (lane >> 4) & 1;
    // dp4a: warps 8..11; cols 80..127 (48), rows wd*32..+31
    const int wd = wid - 8;
    const int gm = lane >> 3;            // 0..3
    const int gn = lane & 7;             // 0..7

    int acc[48];
#pragma unroll
    for (int i = 0; i < 48; i++) acc[i] = 0;

    // Prologue: stages 0 and 1
    load_buf(sb, m0, n0, 0, tid);
    CP_COMMIT();
    load_buf(sb + STAGE_B, m0, n0, 1, tid);
    CP_COMMIT();

    int st = 0;                                      // stage of kc
    for (int kc = 0; kc < NKC; kc++) {
        if (kc < NKC - 1) asm volatile("cp.async.wait_group 1;");
        else              asm volatile("cp.async.wait_group 0;");
        __syncthreads();   // stage st visible; consumers of stage (st+2)%3 done

        if (kc + 2 < NKC) {
            int st2 = st + 2; if (st2 >= 3) st2 -= 3;
            load_buf(sb + (uint32_t)st2 * STAGE_B, m0, n0, kc + 2, tid);
            CP_COMMIT();
        }

        const uint32_t cur = (uint32_t)st * STAGE_B;
        if (is_tc) {
            const uint32_t Ab = sb + cur, Bb = sb + cur + TILE_B;
#pragma unroll
            for (int ks = 0; ks < 4; ks++) {
                const int cb = ks * 2 + lk16;        // 16B chunk 0..7
                uint32_t a[4], b[5][4];
                ldsm_x4(a[0], a[1], a[2], a[3], Ab + swz(wm + lrow, cb));
#pragma unroll
                for (int bt = 0; bt < 5; bt++)
                    ldsm_x4(b[bt][0], b[bt][1], b[bt][2], b[bt][3],
                            Bb + swz(bt * 16 + lrow, cb));
#pragma unroll
                for (int nt = 0; nt < 10; nt++) {
                    const int ix = nt * 4;
                    uint32_t blo = b[nt >> 1][nt & 1];
                    uint32_t bhi = b[nt >> 1][(nt & 1) + 2];
                    mma_s8(acc[ix], acc[ix + 1], acc[ix + 2], acc[ix + 3],
                           a[0], a[1], a[2], a[3], blo, bhi);
                }
            }
        } else {
            const char* Abp = smem + cur;
            const char* Bbp = smem + cur + TILE_B;
#pragma unroll
            for (int kw = 0; kw < 8; kw++) {
                uint4 Bv[6];
#pragma unroll
                for (int c = 0; c < 6; c++)
                    Bv[c] = *reinterpret_cast<const uint4*>(Bbp + swz(80 + c * 8 + gn, kw));
#pragma unroll
                for (int r = 0; r < 8; r++) {
                    const int row = wd * 32 + gm * 2 + (r & 1) + (r >> 1) * 8;
                    uint4 Av = *reinterpret_cast<const uint4*>(Abp + swz(row, kw));
#pragma unroll
                    for (int c = 0; c < 6; c++) {
                        int& a0 = acc[r * 6 + c];
                        a0 = __dp4a((int)Av.x, (int)Bv[c].x, a0);
                        a0 = __dp4a((int)Av.y, (int)Bv[c].y, a0);
                        a0 = __dp4a((int)Av.z, (int)Bv[c].z, a0);
                        a0 = __dp4a((int)Av.w, (int)Bv[c].w, a0);
                    }
                }
            }
        }
        if (++st == 3) st = 0;
    }

    // ----------------------------- epilogue ---------------------------------
    if (is_tc) {
        const int gq = lane >> 2, tg = lane & 3;
#pragma unroll
        for (int nt = 0; nt < 10; nt++) {
            const int ix = nt * 4;
            int col = n0 + nt * 8 + 2 * tg;
            int row0 = m0 + wm + gq;
            float2 v0 = make_float2((float)acc[ix], (float)acc[ix + 1]);
            float2 v1 = make_float2((float)acc[ix + 2], (float)acc[ix + 3]);
            *reinterpret_cast<float2*>(out + (size_t)row0 * O_DIM + col) = v0;
            *reinterpret_cast<float2*>(out + (size_t)(row0 + 8) * O_DIM + col) = v1;
        }
    } else {
#pragma unroll
        for (int r = 0; r < 8; r++) {
            const int row = m0 + wd * 32 + gm * 2 + (r & 1) + (r >> 1) * 8;
#pragma unroll
            for (int c = 0; c < 6; c++) {
                out[(size_t)row * O_DIM + n0 + 80 + c * 8 + gn] = (float)acc[r * 6 + c];
            }
        }
    }
}

// ------------------------------ BatchNorm -----------------------------------
__global__ void bn_zero() {
    int i = blockIdx.x * blockDim.x + threadIdx.x;
    if (i < O_DIM) { g_sum[i] = 0.f; g_ss[i] = 0.f; }
}
__global__ void bn_reduce(const float* __restrict__ d) {
    int col = blockIdx.x * 256 + threadIdx.x;
    const float* p = d + (size_t)blockIdx.y * 256 * O_DIM + col;
    float s = 0.f, ss = 0.f;
#pragma unroll 8
    for (int r = 0; r < 256; r++) {
        float v = p[(size_t)r * O_DIM];
        s += v;
        ss = fmaf(v, v, ss);
    }
    atomicAdd(&g_sum[col], s);
    atomicAdd(&g_ss[col], ss);
}
__global__ void bn_params() {
    int c = blockIdx.x * blockDim.x + threadIdx.x;
    if (c < O_DIM) {
        float mean = g_sum[c] * (1.0f / B_DIM);
        float var = g_ss[c] * (1.0f / B_DIM) - mean * mean;
        float sc = rsqrtf(var + 1e-5f);
        g_scale[c] = sc;
        g_shift[c] = -mean * sc;
    }
}
__global__ void bn_apply(float* __restrict__ d) {
    int i = blockIdx.x * blockDim.x + threadIdx.x;
    float4 v = reinterpret_cast<float4*>(d)[i];
    int c = (i & (O_DIM / 4 - 1)) << 2;
    float4 sc = *reinterpret_cast<const float4*>(g_scale + c);
    float4 sh = *reinterpret_cast<const float4*>(g_shift + c);
    v.x = fmaf(v.x, sc.x, sh.x);
    v.y = fmaf(v.y, sc.y, sh.y);
    v.z = fmaf(v.z, sc.z, sh.z);
    v.w = fmaf(v.w, sc.w, sh.w);
    reinterpret_cast<float4*>(d)[i] = v;
}

// -------------------------------- launch -------------------------------------
extern "C" void kernel_launch(void* const* d_in, const int* in_sizes, int n_in,
                              void* d_out, int out_size) {
    const float* x = (const float*)d_in[0];
    const float* w = (const float*)d_in[1];
    float* out = (float*)d_out;

    cudaFuncSetAttribute(gemm_kernel, cudaFuncAttributeMaxDynamicSharedMemorySize, SMEM_BYTES);

    const int nx16 = B_DIM * K_DIM / 16;
    const int nt16 = nx16 + O_DIM * K_DIM / 16;
    binarize_all<<<(nt16 + 255) / 256, 256>>>(x, w, nx16, nt16);
    bn_zero<<<16, 256>>>();

    gemm_kernel<<<dim3(O_DIM / 128, B_DIM / 128), NTHREADS, SMEM_BYTES>>>(out);

    bn_reduce<<<dim3(O_DIM / 256, B_DIM / 256), 256>>>(out);
    bn_params<<<16, 256>>>();
    bn_apply<<<(B_DIM * O_DIM / 4) / 256, 256>>>(out);
}